// round 17
// baseline (speedup 1.0000x reference)
#include <cuda_runtime.h>
#include <cstdint>
#include <math.h>

#define CLASS_PERIOD 360
#define VEC_PER_ROW  (CLASS_PERIOD / 4)    // 90 float4 per window
#define WARPS_PER_BLOCK 8
#define ROWS_PER_BLOCK (WARPS_PER_BLOCK * 2)    // 16
#define BLOCK_THREADS  (WARPS_PER_BLOCK * 32)   // 256
#define GRID_BLOCKS 1184                   // 8 blocks/SM * 148 SMs: one wave
#define WIN_BYTES (CLASS_PERIOD * 4)       // 1440 B

// Device-global accumulator + ticket (zeroed at load; last block resets them
// after all contributions are published -> graph-replay safe).
__device__ float        g_accum  = 0.0f;
__device__ unsigned int g_ticket = 0;

__device__ __forceinline__ uint32_t smem_u32(const void* p) {
    uint32_t a;
    asm("{ .reg .u64 t; cvta.to.shared.u64 t, %1; cvt.u32.u64 %0, t; }"
        : "=r"(a) : "l"(p));
    return a;
}

// ---------------------------------------------------------------------------
// Hybrid load path: preds via LDG.128 (6/thread), labels via per-warp TMA
// bulk copies into smem (halves the SM-wide outstanding-LDG population).
// 2 rows per warp (half-warp each); exp-sum computed while labels fly.
// Champion epilogue: block partial -> relaxed RED + acq_rel ticket.
// ---------------------------------------------------------------------------
__global__ __launch_bounds__(BLOCK_THREADS, 8)
void vp_fused_kernel(const float* __restrict__ preds,
                     const float* __restrict__ labels,
                     const int*   __restrict__ obj_classes,  // int32
                     float* __restrict__ out,
                     int W, int B)
{
    __shared__ __align__(16) float s_l[ROWS_PER_BLOCK][CLASS_PERIOD];
    __shared__ __align__(8)  unsigned long long s_mbar[WARPS_PER_BLOCK];
    __shared__ float s_row[ROWS_PER_BLOCK];

    const int tid    = threadIdx.x;
    const int lane   = tid & 31;
    const int warp   = tid >> 5;
    const int lane16 = lane & 15;
    const int half   = lane >> 4;
    const int nblocks = gridDim.x;

    const int ntasks = B >> 1;                       // 8192 row pairs
    const int task   = warp * nblocks + blockIdx.x;  // transposed map
    const bool active = (task < ntasks);

    float part = 0.0f;
    const uint32_t mbar = smem_u32(&s_mbar[warp]);

    float4 pv0, pv1, pv2, pv3, pv4, pv5;
    const float4* l4 = (const float4*)&s_l[warp * 2 + half][0];
    bool a5 = false;
    float es = 0.0f;

    if (active) {
        const int row = task * 2 + half;
        const long long base = (long long)row * (long long)W
                             + (long long)obj_classes[row] * CLASS_PERIOD;
        const float4* __restrict__ p4 = (const float4*)(preds  + base);

        // --- per-warp mbarrier init (lane 0), visible to async proxy -------
        if (lane == 0) {
            asm volatile("mbarrier.init.shared.b64 [%0], %1;"
                         :: "r"(mbar), "r"(2) : "memory");
            asm volatile("fence.proxy.async.shared::cta;" ::: "memory");
        }
        __syncwarp();

        // --- lanes 0 and 16: arrive+expect_tx, issue this row's label copy -
        if (lane16 == 0) {
            asm volatile("mbarrier.arrive.expect_tx.shared.b64 _, [%0], %1;"
                         :: "r"(mbar), "r"((uint32_t)WIN_BYTES) : "memory");
            asm volatile(
                "cp.async.bulk.shared::cta.global.mbarrier::complete_tx::bytes "
                "[%0], [%1], %2, [%3];"
                :: "r"(smem_u32(&s_l[warp * 2 + half][0])),
                   "l"(labels + base), "r"((uint32_t)WIN_BYTES), "r"(mbar)
                : "memory");
        }

        // --- preds via LDG.128 while labels fly on TMA ---------------------
        a5 = (lane16 + 80) < VEC_PER_ROW;    // lane16 < 10
        pv0 = p4[lane16];
        pv1 = p4[lane16 + 16];
        pv2 = p4[lane16 + 32];
        pv3 = p4[lane16 + 48];
        pv4 = p4[lane16 + 64];
        pv5 = make_float4(0.f, 0.f, 0.f, 0.f);
        if (a5) pv5 = p4[lane16 + 80];

        // exp-sum needs only preds: overlap with the TMA transfer.
        es = __expf(pv0.x) + __expf(pv0.y) + __expf(pv0.z) + __expf(pv0.w)
           + __expf(pv1.x) + __expf(pv1.y) + __expf(pv1.z) + __expf(pv1.w)
           + __expf(pv2.x) + __expf(pv2.y) + __expf(pv2.z) + __expf(pv2.w)
           + __expf(pv3.x) + __expf(pv3.y) + __expf(pv3.z) + __expf(pv3.w)
           + __expf(pv4.x) + __expf(pv4.y) + __expf(pv4.z) + __expf(pv4.w);
        if (a5)
            es += __expf(pv5.x) + __expf(pv5.y) + __expf(pv5.z) + __expf(pv5.w);

        // --- wait for this warp's labels (acquire orders the LDS below) ----
        {
            uint32_t done;
            asm volatile(
                "{\n\t.reg .pred p;\n\t"
                "mbarrier.try_wait.parity.acquire.cta.shared::cta.b64 p, [%1], %2;\n\t"
                "selp.b32 %0, 1, 0, p;\n\t}"
                : "=r"(done) : "r"(mbar), "r"(0u) : "memory");
            if (!done) {
                asm volatile(
                    "{\n\t.reg .pred P1;\n\t"
                    "WL_%=:\n\t"
                    "mbarrier.try_wait.parity.acquire.cta.shared::cta.b64 P1, [%0], %1, 0x989680;\n\t"
                    "@P1 bra.uni WD_%=;\n\t"
                    "bra.uni WL_%=;\n\t"
                    "WD_%=:\n\t}"
                    :: "r"(mbar), "r"(0u) : "memory");
            }
        }

        // --- dt / ls from smem labels --------------------------------------
        float4 lv0 = l4[lane16];
        float4 lv1 = l4[lane16 + 16];
        float4 lv2 = l4[lane16 + 32];
        float4 lv3 = l4[lane16 + 48];
        float4 lv4 = l4[lane16 + 64];
        float4 lv5 = make_float4(0.f, 0.f, 0.f, 0.f);
        if (a5) lv5 = l4[lane16 + 80];

        float dt = lv0.x*pv0.x + lv0.y*pv0.y + lv0.z*pv0.z + lv0.w*pv0.w
                 + lv1.x*pv1.x + lv1.y*pv1.y + lv1.z*pv1.z + lv1.w*pv1.w
                 + lv2.x*pv2.x + lv2.y*pv2.y + lv2.z*pv2.z + lv2.w*pv2.w
                 + lv3.x*pv3.x + lv3.y*pv3.y + lv3.z*pv3.z + lv3.w*pv3.w
                 + lv4.x*pv4.x + lv4.y*pv4.y + lv4.z*pv4.z + lv4.w*pv4.w;
        float ls = lv0.x + lv0.y + lv0.z + lv0.w
                 + lv1.x + lv1.y + lv1.z + lv1.w
                 + lv2.x + lv2.y + lv2.z + lv2.w
                 + lv3.x + lv3.y + lv3.z + lv3.w
                 + lv4.x + lv4.y + lv4.z + lv4.w;
        if (a5) {
            dt += lv5.x*pv5.x + lv5.y*pv5.y + lv5.z*pv5.z + lv5.w*pv5.w;
            ls += lv5.x + lv5.y + lv5.z + lv5.w;
        }

        // Half-warp reduction (xor 8,4,2,1 stays within each 16-lane half).
        #pragma unroll
        for (int off = 8; off > 0; off >>= 1) {
            es += __shfl_xor_sync(0xFFFFFFFFu, es, off);
            dt += __shfl_xor_sync(0xFFFFFFFFu, dt, off);
            ls += __shfl_xor_sync(0xFFFFFFFFu, ls, off);
        }

        part = dt - __logf(es) * ls;   // sum_j l_j*log_softmax(p)_j
    }

    // ---------------- block partial -> device accumulator ------------------
    if (lane16 == 0)                      // lanes 0 and 16 (idle warps write 0)
        s_row[warp * 2 + half] = part;
    __syncthreads();

    if (tid == 0) {
        float bp = 0.0f;
        #pragma unroll
        for (int w = 0; w < ROWS_PER_BLOCK; w++) bp += s_row[w];

        atomicAdd(&g_accum, bp);               // relaxed RED at L2

        unsigned int t;
        asm volatile("atom.acq_rel.gpu.global.add.u32 %0, [%1], 1;"
                     : "=r"(t) : "l"(&g_ticket) : "memory");
        if (t == (unsigned)(nblocks - 1)) {
            float acc;
            asm volatile("ld.acquire.gpu.global.f32 %0, [%1];"
                         : "=f"(acc) : "l"(&g_accum) : "memory");
            out[0] = -acc / ((float)CLASS_PERIOD * (float)B);
            g_accum = 0.0f;                    // reset for next graph replay
            asm volatile("st.relaxed.gpu.global.u32 [%0], %1;"
                         :: "l"(&g_ticket), "r"(0u) : "memory");
        }
    }
}

// ---------------------------------------------------------------------------
extern "C" void kernel_launch(void* const* d_in, const int* in_sizes, int n_in,
                              void* d_out, int out_size)
{
    const float* preds  = (const float*)d_in[0];
    const float* labels = (const float*)d_in[1];
    const int*   objcls = (const int*)d_in[2];

    const int B = in_sizes[2];                // 16384
    const int W = in_sizes[0] / B;            // 4320

    vp_fused_kernel<<<GRID_BLOCKS, BLOCK_THREADS>>>(preds, labels, objcls,
                                                    (float*)d_out, W, B);
}